// round 1
// baseline (speedup 1.0000x reference)
#include <cuda_runtime.h>
#include <cuda_bf16.h>

// Problem constants (fixed by the dataset)
#define BS 16
#define LQ 300
#define DM 256
#define NH 8
#define NC 32
#define NP 16
#define LV 8500
#define NOUT 384   // 256 offset outputs + 128 attn outputs
#define BQ (BS * LQ)   // 4800

// Scratch: projection results [4800][384] (off: cols 0..255, attn logits: 256..383)
__device__ float g_proj[BQ * NOUT];

// ---------------------------------------------------------------------------
// Kernel 1: C[4800,384] = Q[4800,256] @ [W_off;W_attn]^T + bias
// Tiled 64x64, BK=16, 256 threads, 4x4 per thread.
// ---------------------------------------------------------------------------
__global__ __launch_bounds__(256) void proj_kernel(
    const float* __restrict__ Q,
    const float* __restrict__ Woff, const float* __restrict__ boff,
    const float* __restrict__ Wattn, const float* __restrict__ battn)
{
    __shared__ float As[16][68];
    __shared__ float Bs[16][68];
    const int bm = blockIdx.x * 64;
    const int bn = blockIdx.y * 64;
    const int t  = threadIdx.x;
    const int tx = t & 15, ty = t >> 4;
    const int lr = t >> 2;          // row 0..63 for loading
    const int lk = (t & 3) * 4;     // k offset 0,4,8,12

    const int o = bn + lr;
    const float* Brow = (o < 256) ? (Woff + o * DM) : (Wattn + (o - 256) * DM);
    const float* Arow = Q + (bm + lr) * DM;

    float acc[4][4] = {};

    for (int k0 = 0; k0 < DM; k0 += 16) {
        float4 av = *(const float4*)(Arow + k0 + lk);
        float4 bv = *(const float4*)(Brow + k0 + lk);
        As[lk + 0][lr] = av.x; As[lk + 1][lr] = av.y;
        As[lk + 2][lr] = av.z; As[lk + 3][lr] = av.w;
        Bs[lk + 0][lr] = bv.x; Bs[lk + 1][lr] = bv.y;
        Bs[lk + 2][lr] = bv.z; Bs[lk + 3][lr] = bv.w;
        __syncthreads();
        #pragma unroll
        for (int kk = 0; kk < 16; kk++) {
            float4 a = *(const float4*)&As[kk][ty * 4];
            float4 b = *(const float4*)&Bs[kk][tx * 4];
            float ar[4] = {a.x, a.y, a.z, a.w};
            float br[4] = {b.x, b.y, b.z, b.w};
            #pragma unroll
            for (int i = 0; i < 4; i++)
                #pragma unroll
                for (int j = 0; j < 4; j++)
                    acc[i][j] += ar[i] * br[j];
        }
        __syncthreads();
    }

    #pragma unroll
    for (int j = 0; j < 4; j++) {
        int oc = bn + tx * 4 + j;
        float bias = (oc < 256) ? boff[oc] : battn[oc - 256];
        #pragma unroll
        for (int i = 0; i < 4; i++)
            g_proj[(bm + ty * 4 + i) * NOUT + oc] = acc[i][j] + bias;
    }
}

// ---------------------------------------------------------------------------
// Kernel 2: per (b,q) block. Phase 1 (threads 0..127): locations + softmax.
// Phase 2 (all 256 = head*32+channel): bilinear gather + weighted sum.
// ---------------------------------------------------------------------------
__global__ __launch_bounds__(256) void sample_kernel(
    const float* __restrict__ refp,
    const float* __restrict__ value,
    float* __restrict__ out)
{
    const int bq = blockIdx.x;           // b*300 + q
    const int b  = bq / LQ;
    const int t  = threadIdx.x;

    __shared__ float sx[NH * NP];
    __shared__ float sy[NH * NP];
    __shared__ float saw[NH * NP];

    if (t < NH * NP) {
        // t = h*16 + p
        const int p = t & 15;
        const float offx  = g_proj[bq * NOUT + 2 * t];
        const float offy  = g_proj[bq * NOUT + 2 * t + 1];
        const float logit = g_proj[bq * NOUT + 256 + t];
        const float* rp = refp + bq * 4;
        const float locx = rp[0] + offx * 0.125f * rp[2];  // nps(0.25)*scale(0.5)
        const float locy = rp[1] + offy * 0.125f * rp[3];
        const int lvl = p >> 2;
        const float wl = (float)(80 >> lvl);
        const float hl = (float)(80 >> lvl);
        sx[t] = locx * wl - 0.5f;
        sy[t] = locy * hl - 0.5f;
        // softmax over the 16 points of this head (16-lane segments)
        float m = logit;
        #pragma unroll
        for (int d = 8; d > 0; d >>= 1)
            m = fmaxf(m, __shfl_xor_sync(0xffffffffu, m, d, 16));
        float e = __expf(logit - m);
        float s = e;
        #pragma unroll
        for (int d = 8; d > 0; d >>= 1)
            s += __shfl_xor_sync(0xffffffffu, s, d, 16);
        saw[t] = e / s;
    }
    __syncthreads();

    const int h  = t >> 5;      // head
    const int ch = t & 31;      // channel
    const float* vb = value + (size_t)b * LV * (NH * NC);

    const int lw[4]    = {80, 40, 20, 10};
    const int lstart[4] = {0, 6400, 8000, 8400};

    float acc = 0.f;
    #pragma unroll
    for (int p = 0; p < NP; p++) {
        const int lvl = p >> 2;
        const int w  = lw[lvl];
        const int hh = lw[lvl];
        const int base = lstart[lvl];
        const int si = h * NP + p;
        const float x = sx[si], y = sy[si], aw = saw[si];

        const float x0f = floorf(x), y0f = floorf(y);
        const int x0 = (int)x0f, y0 = (int)y0f;
        const float wx1 = x - x0f, wy1 = y - y0f;
        const float wx0 = 1.f - wx1, wy0 = 1.f - wy1;

        const bool xv0 = (x0 >= 0) && (x0 < w);
        const bool xv1 = (x0 + 1 >= 0) && (x0 + 1 < w);
        const bool yv0 = (y0 >= 0) && (y0 < hh);
        const bool yv1 = (y0 + 1 >= 0) && (y0 + 1 < hh);

        float v = 0.f;
        if (yv0) {
            const float* rowp = vb + (size_t)(base + y0 * w) * (NH * NC) + h * NC + ch;
            if (xv0) v += wx0 * wy0 * __ldg(rowp + x0 * (NH * NC));
            if (xv1) v += wx1 * wy0 * __ldg(rowp + (x0 + 1) * (NH * NC));
        }
        if (yv1) {
            const float* rowp = vb + (size_t)(base + (y0 + 1) * w) * (NH * NC) + h * NC + ch;
            if (xv0) v += wx0 * wy1 * __ldg(rowp + x0 * (NH * NC));
            if (xv1) v += wx1 * wy1 * __ldg(rowp + (x0 + 1) * (NH * NC));
        }
        acc += aw * v;
    }
    out[(size_t)bq * (NH * NC) + t] = acc;
}

// ---------------------------------------------------------------------------
extern "C" void kernel_launch(void* const* d_in, const int* in_sizes, int n_in,
                              void* d_out, int out_size)
{
    const float* query = (const float*)d_in[0];
    const float* refp  = (const float*)d_in[1];
    const float* value = (const float*)d_in[2];
    const float* Woff  = (const float*)d_in[3];
    const float* boff  = (const float*)d_in[4];
    const float* Wattn = (const float*)d_in[5];
    const float* battn = (const float*)d_in[6];
    float* out = (float*)d_out;

    dim3 g1(BQ / 64, NOUT / 64);   // (75, 6)
    proj_kernel<<<g1, 256>>>(query, Woff, boff, Wattn, battn);
    sample_kernel<<<BQ, 256>>>(refp, value, out);
}

// round 2
// speedup vs baseline: 1.3926x; 1.3926x over previous
#include <cuda_runtime.h>
#include <cuda_bf16.h>

// Problem constants (fixed by the dataset)
#define BS 16
#define LQ 300
#define DM 256
#define NH 8
#define NC 32
#define NP 16
#define LV 8500
#define NOUT 384
#define BQ (BS * LQ)   // 4800

typedef unsigned long long ull;

// Scratch: projection results [4800][384] (off: cols 0..255, attn logits: 256..383)
__device__ float g_proj[BQ * NOUT];

__device__ __forceinline__ ull dup2(float v) {
    ull r;
    asm("mov.b64 %0, {%1, %1};" : "=l"(r) : "f"(v));
    return r;
}
__device__ __forceinline__ void fma2(ull& d, ull a, ull b) {
    asm("fma.rn.f32x2 %0, %1, %2, %0;" : "+l"(d) : "l"(a), "l"(b));
}
__device__ __forceinline__ float2 unpack2(ull v) {
    float2 r;
    asm("mov.b64 {%0, %1}, %2;" : "=f"(r.x), "=f"(r.y) : "l"(v));
    return r;
}

// ---------------------------------------------------------------------------
// Kernel 1: C[4800,384] = Q[4800,256] @ [W_off;W_attn]^T + bias
// 64x64 tile, BK=16, 256 threads, per-thread 4x4 via packed f32x2 FMA
// (accumulate row-pairs in 64-bit regs -> halves FFMA issue count).
// ---------------------------------------------------------------------------
__global__ __launch_bounds__(256) void proj_kernel(
    const float* __restrict__ Q,
    const float* __restrict__ Woff, const float* __restrict__ boff,
    const float* __restrict__ Wattn, const float* __restrict__ battn)
{
    __shared__ float As[16][72];   // k-major: As[kk][row], 16B-aligned rows
    __shared__ float Bs[16][72];
    const int bm = blockIdx.x * 64;
    const int bn = blockIdx.y * 64;
    const int t  = threadIdx.x;
    const int tx = t & 15, ty = t >> 4;     // cols tx*4.., rows ty*4..
    const int lr = t >> 2;                  // load row/col 0..63
    const int lk = (t & 3) * 4;             // k offset 0,4,8,12

    const int o = bn + lr;
    const float* Brow = (o < 256) ? (Woff + o * DM) : (Wattn + (o - 256) * DM);
    const float* Arow = Q + (bm + lr) * DM;

    // acc[rowpair 0..1][col 0..3], each holds rows (2rp, 2rp+1) packed
    ull acc[2][4] = {};

    for (int k0 = 0; k0 < DM; k0 += 16) {
        float4 av = *(const float4*)(Arow + k0 + lk);
        float4 bv = *(const float4*)(Brow + k0 + lk);
        As[lk + 0][lr] = av.x; As[lk + 1][lr] = av.y;
        As[lk + 2][lr] = av.z; As[lk + 3][lr] = av.w;
        Bs[lk + 0][lr] = bv.x; Bs[lk + 1][lr] = bv.y;
        Bs[lk + 2][lr] = bv.z; Bs[lk + 3][lr] = bv.w;
        __syncthreads();
        #pragma unroll
        for (int kk = 0; kk < 16; kk++) {
            ulonglong2 a = *(const ulonglong2*)&As[kk][ty * 4]; // rows(0,1),(2,3)
            float4 b = *(const float4*)&Bs[kk][tx * 4];
            ull b0 = dup2(b.x), b1 = dup2(b.y), b2 = dup2(b.z), b3 = dup2(b.w);
            fma2(acc[0][0], a.x, b0); fma2(acc[1][0], a.y, b0);
            fma2(acc[0][1], a.x, b1); fma2(acc[1][1], a.y, b1);
            fma2(acc[0][2], a.x, b2); fma2(acc[1][2], a.y, b2);
            fma2(acc[0][3], a.x, b3); fma2(acc[1][3], a.y, b3);
        }
        __syncthreads();
    }

    #pragma unroll
    for (int j = 0; j < 4; j++) {
        const int oc = bn + tx * 4 + j;
        const float bias = (oc < 256) ? boff[oc] : battn[oc - 256];
        #pragma unroll
        for (int rp = 0; rp < 2; rp++) {
            float2 v = unpack2(acc[rp][j]);
            const int r0 = bm + ty * 4 + 2 * rp;
            g_proj[(r0 + 0) * NOUT + oc] = v.x + bias;
            g_proj[(r0 + 1) * NOUT + oc] = v.y + bias;
        }
    }
}

// ---------------------------------------------------------------------------
// Kernel 2: one block per (b,q), 128 threads.
// Phase 1 (t = h*16+p): loc + softmax + corner idx/weights -> smem.
//   Indices pre-scaled by row stride (256), clamped; weights combined with
//   the attention weight and zeroed for invalid corners (branch-free phase 2).
// Phase 2 (t = h*16 + channel-pair): 16 pts x 4 corners float2 gather-FMA.
// ---------------------------------------------------------------------------
__global__ __launch_bounds__(128) void sample_kernel(
    const float* __restrict__ refp,
    const float* __restrict__ value,
    float* __restrict__ out)
{
    const int bq = blockIdx.x;
    const int b  = bq / LQ;
    const int t  = threadIdx.x;

    __shared__ int4   sidx[NH * NP];
    __shared__ float4 swt[NH * NP];

    {
        const int p = t & 15;
        const float2 off  = *(const float2*)&g_proj[bq * NOUT + 2 * t];
        const float logit = g_proj[bq * NOUT + 256 + t];
        const float4 rp   = *(const float4*)(refp + bq * 4);
        const float locx = rp.x + off.x * 0.125f * rp.z;  // nps(0.25)*scale(0.5)
        const float locy = rp.y + off.y * 0.125f * rp.w;

        const int lvl = p >> 2;
        const int w = 80 >> lvl;
        const int lstart[4] = {0, 6400, 8000, 8400};
        const int base = lstart[lvl];

        const float x = locx * (float)w - 0.5f;
        const float y = locy * (float)w - 0.5f;
        const float x0f = floorf(x), y0f = floorf(y);
        const int x0 = (int)x0f, y0 = (int)y0f;
        const float wx1 = x - x0f, wy1 = y - y0f;
        const float wx0 = 1.f - wx1, wy0 = 1.f - wy1;

        // softmax over 16 points of this head
        float m = logit;
        #pragma unroll
        for (int d = 8; d > 0; d >>= 1)
            m = fmaxf(m, __shfl_xor_sync(0xffffffffu, m, d, 16));
        const float e = __expf(logit - m);
        float s = e;
        #pragma unroll
        for (int d = 8; d > 0; d >>= 1)
            s += __shfl_xor_sync(0xffffffffu, s, d, 16);
        const float aw = e / s;

        const bool xv0 = (x0 >= 0) && (x0 < w);
        const bool xv1 = (x0 + 1 >= 0) && (x0 + 1 < w);
        const bool yv0 = (y0 >= 0) && (y0 < w);
        const bool yv1 = (y0 + 1 >= 0) && (y0 + 1 < w);
        const int xc0 = min(max(x0, 0), w - 1);
        const int xc1 = min(max(x0 + 1, 0), w - 1);
        const int yc0 = min(max(y0, 0), w - 1);
        const int yc1 = min(max(y0 + 1, 0), w - 1);

        sidx[t] = make_int4((base + yc0 * w + xc0) * 256,
                            (base + yc0 * w + xc1) * 256,
                            (base + yc1 * w + xc0) * 256,
                            (base + yc1 * w + xc1) * 256);
        swt[t] = make_float4((xv0 && yv0) ? aw * wx0 * wy0 : 0.f,
                             (xv1 && yv0) ? aw * wx1 * wy0 : 0.f,
                             (xv0 && yv1) ? aw * wx0 * wy1 : 0.f,
                             (xv1 && yv1) ? aw * wx1 * wy1 : 0.f);
    }
    __syncthreads();

    const int h  = t >> 4;       // head
    const int c2 = t & 15;       // channel pair
    const float* vb = value + (size_t)b * LV * (NH * NC) + h * NC + c2 * 2;

    float ax = 0.f, ay = 0.f;
    #pragma unroll
    for (int p = 0; p < NP; p++) {
        const int4   i4 = sidx[h * NP + p];
        const float4 w4 = swt[h * NP + p];
        float2 v;
        v = *(const float2*)(vb + i4.x); ax += w4.x * v.x; ay += w4.x * v.y;
        v = *(const float2*)(vb + i4.y); ax += w4.y * v.x; ay += w4.y * v.y;
        v = *(const float2*)(vb + i4.z); ax += w4.z * v.x; ay += w4.z * v.y;
        v = *(const float2*)(vb + i4.w); ax += w4.w * v.x; ay += w4.w * v.y;
    }
    *(float2*)(out + (size_t)bq * (NH * NC) + h * NC + c2 * 2) = make_float2(ax, ay);
}

// ---------------------------------------------------------------------------
extern "C" void kernel_launch(void* const* d_in, const int* in_sizes, int n_in,
                              void* d_out, int out_size)
{
    const float* query = (const float*)d_in[0];
    const float* refp  = (const float*)d_in[1];
    const float* value = (const float*)d_in[2];
    const float* Woff  = (const float*)d_in[3];
    const float* boff  = (const float*)d_in[4];
    const float* Wattn = (const float*)d_in[5];
    const float* battn = (const float*)d_in[6];
    float* out = (float*)d_out;

    dim3 g1(BQ / 64, NOUT / 64);   // (75, 6)
    proj_kernel<<<g1, 256>>>(query, Woff, boff, Wattn, battn);
    sample_kernel<<<BQ, 128>>>(refp, value, out);
}